// round 5
// baseline (speedup 1.0000x reference)
#include <cuda_runtime.h>
#include <cuda_fp16.h>
#include <mma.h>
#include <math.h>

using namespace nvcuda;

#define N_NODES 100000
#define N_EDGES 1600000
#define F_IN    128
#define F_E     32
#define DH      128   // D*H
#define NH      4     // heads
#define FULLM   0xffffffffu
#define SCAN_BLOCKS 98   // ceil(100000/1024)

// -------- scratch (static device globals; no allocation allowed) --------
__device__ __half2 g_np_h[(size_t)N_NODES * 64];      // node_proj fp16, 25.6 MB
__device__ __half  g_W_h[F_IN * DH];                  // W_node in fp16
__device__ float g_ssrc[N_NODES * NH];
__device__ float g_v[NH * F_E];                       // folded W_edge @ a_edge
__device__ int g_cnt[N_NODES];
__device__ int g_rowptr[N_NODES + 1];
__device__ int g_head[N_NODES];
__device__ int g_part[128];
struct alignas(32) Rec { float4 p; int src; int pad0, pad1, pad2; };
__device__ Rec g_rec[N_EDGES];                        // 51.2 MB, dst-sorted

// -------- prep: fold W_edge@a_edge into g_v; convert W_node to fp16 --------
__global__ void __launch_bounds__(256) k_prep(const float* __restrict__ W_edge,
                                              const float* __restrict__ AK,
                                              const float* __restrict__ Wn) {
    int t = threadIdx.x;
    if (t < 128) {
        int h = t >> 5, k = t & 31;
        float s = 0.f;
#pragma unroll
        for (int d = 0; d < 32; d++)
            s += W_edge[k * DH + h * 32 + d] * AK[h * 96 + 64 + d];
        g_v[h * 32 + k] = s;
    }
    for (int i = t; i < F_IN * DH; i += 256)
        g_W_h[i] = __float2half_rn(Wn[i]);
}

__global__ void k_zero_cnt() {
    int i = blockIdx.x * blockDim.x + threadIdx.x;
    if (i < N_NODES) g_cnt[i] = 0;
}

__global__ void __launch_bounds__(256) k_hist(const int* __restrict__ EI) {
    int e = blockIdx.x * 256 + threadIdx.x;
    int2 ei = reinterpret_cast<const int2*>(EI)[e];
    atomicAdd(&g_cnt[ei.y], 1);
}

// -------- scan stage 1: per-block exclusive scan + block totals --------
__global__ void __launch_bounds__(1024) k_scan_blocks() {
    __shared__ int s[1024];
    int t = threadIdx.x;
    int i = blockIdx.x * 1024 + t;
    int v = (i < N_NODES) ? g_cnt[i] : 0;
    s[t] = v;
    __syncthreads();
    for (int o = 1; o < 1024; o <<= 1) {
        int u = (t >= o) ? s[t - o] : 0;
        __syncthreads();
        s[t] += u;
        __syncthreads();
    }
    if (i < N_NODES) g_rowptr[i] = s[t] - v;
    if (t == 1023) g_part[blockIdx.x] = s[1023];
}

__global__ void k_scan_part() {
    __shared__ int s[128];
    int t = threadIdx.x;
    int v = (t < SCAN_BLOCKS) ? g_part[t] : 0;
    s[t] = v;
    __syncthreads();
    for (int o = 1; o < 128; o <<= 1) {
        int u = (t >= o) ? s[t - o] : 0;
        __syncthreads();
        s[t] += u;
        __syncthreads();
    }
    if (t < SCAN_BLOCKS) g_part[t] = s[t] - v;
    if (t == 0) g_rowptr[N_NODES] = N_EDGES;
}

__global__ void __launch_bounds__(1024) k_scan_add() {
    int i = blockIdx.x * 1024 + threadIdx.x;
    if (i < N_NODES) {
        int r = g_rowptr[i] + g_part[blockIdx.x];
        g_rowptr[i] = r;
        g_head[i] = r;
    }
}

// -------- node_proj = NF @ W_node via wmma (fp16 in, fp32 acc) --------
// block: 256 thr = 8 warps; tile 64 rows x 128 cols.
// warp (wm = w>>1 in 0..3, wn = w&1 in 0..1) -> rows wm*16, cols wn*64 (4 frags)
__global__ void __launch_bounds__(256) k_node_gemm(const float* __restrict__ NF,
                                                   const float* __restrict__ AK) {
    __shared__ __half sA[64 * 128];   // 16 KB
    __shared__ float  sC[64 * 128];   // 32 KB  (total exactly 48 KB)
    int t = threadIdx.x;
    int row0 = blockIdx.x * 64;

    // load + convert A tile: 2048 float4 -> 256 thr x 8 iters
#pragma unroll
    for (int i = 0; i < 8; i++) {
        int idx = i * 256 + t;          // float4 index
        int r = idx >> 5, c4 = idx & 31;
        int gr = row0 + r;
        float4 v = (gr < N_NODES)
            ? reinterpret_cast<const float4*>(NF)[(size_t)gr * 32 + c4]
            : make_float4(0.f, 0.f, 0.f, 0.f);
        __half2 h01 = __floats2half2_rn(v.x, v.y);
        __half2 h23 = __floats2half2_rn(v.z, v.w);
        uint2 raw;
        raw.x = *reinterpret_cast<unsigned*>(&h01);
        raw.y = *reinterpret_cast<unsigned*>(&h23);
        reinterpret_cast<uint2*>(sA)[idx] = raw;
    }
    __syncthreads();

    int w = t >> 5;
    int wm = w >> 1, wn = w & 1;

    wmma::fragment<wmma::accumulator, 16, 16, 16, float> c[4];
#pragma unroll
    for (int j = 0; j < 4; j++) wmma::fill_fragment(c[j], 0.f);

#pragma unroll
    for (int k = 0; k < 8; k++) {
        wmma::fragment<wmma::matrix_a, 16, 16, 16, __half, wmma::row_major> a;
        wmma::load_matrix_sync(a, sA + (wm * 16) * 128 + k * 16, 128);
#pragma unroll
        for (int j = 0; j < 4; j++) {
            wmma::fragment<wmma::matrix_b, 16, 16, 16, __half, wmma::row_major> b;
            wmma::load_matrix_sync(b, g_W_h + (k * 16) * 128 + wn * 64 + j * 16, 128);
            wmma::mma_sync(c[j], a, b, c[j]);
        }
    }
#pragma unroll
    for (int j = 0; j < 4; j++)
        wmma::store_matrix_sync(sC + (wm * 16) * 128 + wn * 64 + j * 16, c[j],
                                128, wmma::mem_row_major);
    __syncthreads();

    // epilogue: fp16 store of node_proj + fused s_src score (s_dst cancels)
    int tx = t & 31, ty = t >> 5;
    int h = tx >> 3;
    int dl = (tx & 7) * 4;
    const float* a_s = AK + h * 96;
#pragma unroll
    for (int i = 0; i < 8; i++) {
        int gr = row0 + ty * 8 + i;
        float4 v = *reinterpret_cast<const float4*>(&sC[(ty * 8 + i) * 128 + tx * 4]);
        if (gr < N_NODES) {
            __half2 h01 = __floats2half2_rn(v.x, v.y);
            __half2 h23 = __floats2half2_rn(v.z, v.w);
            uint2 raw;
            raw.x = *reinterpret_cast<unsigned*>(&h01);
            raw.y = *reinterpret_cast<unsigned*>(&h23);
            reinterpret_cast<uint2*>(g_np_h)[(size_t)gr * 32 + tx] = raw;
        }
        float ps = v.x * a_s[dl] + v.y * a_s[dl + 1]
                 + v.z * a_s[dl + 2] + v.w * a_s[dl + 3];
#pragma unroll
        for (int o = 4; o >= 1; o >>= 1)
            ps += __shfl_down_sync(FULLM, ps, o, 8);
        if ((tx & 7) == 0 && gr < N_NODES)
            g_ssrc[gr * 4 + h] = ps;
    }
}

// -------- permute pass: p = exp(s_src[src]+s_edge), counting-sort by dst ----
__global__ void __launch_bounds__(256) k_permute(const int* __restrict__ EI,
                                                 const float* __restrict__ EF) {
    __shared__ float sef[64 * 36];
    __shared__ float sv[128];
    __shared__ int2  sEI[64];
    __shared__ float sp[256];
    int t = threadIdx.x;
    int e0 = blockIdx.x * 64;
    if (t < 128) sv[t] = g_v[t];
    if (t < 64)  sEI[t] = reinterpret_cast<const int2*>(EI)[e0 + t];
#pragma unroll
    for (int i = 0; i < 2; i++) {
        int idx = i * 256 + t;
        int el = idx >> 3, c4 = idx & 7;
        float4 v = reinterpret_cast<const float4*>(EF + (size_t)(e0 + el) * F_E)[c4];
        *reinterpret_cast<float4*>(&sef[el * 36 + c4 * 4]) = v;
    }
    __syncthreads();

    {   // thread = (edge, head)
        int el = t >> 2, h = t & 3;
        int2 ei = sEI[el];
        const float* vh = sv + h * 32;
        float se = 0.f;
#pragma unroll
        for (int j = 0; j < 32; j++) se += sef[el * 36 + j] * vh[j];
        sp[t] = __expf(g_ssrc[ei.x * 4 + h] + se);
    }
    __syncthreads();

    if (t < 64) {
        int2 ei = sEI[t];
        int pos = atomicAdd(&g_head[ei.y], 1);
        g_rec[pos].p = *reinterpret_cast<float4*>(&sp[t * 4]);
        g_rec[pos].src = ei.x;
    }
}

// -------- fused gather-aggregate + softmax-normalize + W_out + gelu --------
__global__ void __launch_bounds__(256) k_agg_out(const float* __restrict__ Wo,
                                                 const float* __restrict__ bo,
                                                 float* __restrict__ out) {
    __shared__ float sWt[32 * 132];   // W_out transposed [col][k], padded
    __shared__ float sb[32];
    __shared__ float s_p[8 * 128];
    __shared__ int   s_src[8 * 32];
    __shared__ float s_A[8 * 128];
    int t = threadIdx.x, lane = t & 31, w = t >> 5;
    for (int idx = t; idx < 4096; idx += 256) {
        int k = idx >> 5, col = idx & 31;
        sWt[col * 132 + k] = Wo[idx];
    }
    if (t < 32) sb[t] = bo[t];
    __syncthreads();

    float* wp = s_p + w * 128;
    int* wsrc = s_src + w * 32;
    float* wA = s_A + w * 128;
    int h = lane >> 3;
    const uint2* np2 = reinterpret_cast<const uint2*>(g_np_h);

    for (int n = blockIdx.x * 8 + w; n < N_NODES; n += gridDim.x * 8) {
        int beg = g_rowptr[n];
        int end = g_rowptr[n + 1];
        float a0 = 0.f, a1 = 0.f, a2 = 0.f, a3 = 0.f, ds = 0.f;

        for (int j0 = beg; j0 < end; j0 += 32) {
            int j = j0 + lane;
            if (j < end) {
                *reinterpret_cast<float4*>(&wp[lane * 4]) = g_rec[j].p;
                wsrc[lane] = g_rec[j].src;
            }
            __syncwarp();
            int m = min(32, end - j0);
#pragma unroll 4
            for (int q = 0; q < m; q++) {
                int src = wsrc[q];
                float ph = wp[q * 4 + h];
                uint2 raw = np2[(size_t)src * 32 + lane];
                float2 f01 = __half22float2(*reinterpret_cast<__half2*>(&raw.x));
                float2 f23 = __half22float2(*reinterpret_cast<__half2*>(&raw.y));
                a0 += ph * f01.x;
                a1 += ph * f01.y;
                a2 += ph * f23.x;
                a3 += ph * f23.y;
                ds += ph;
            }
            __syncwarp();
        }

        float inv = 1.f / (ds + 1e-8f);
        float4 av = make_float4(a0 * inv, a1 * inv, a2 * inv, a3 * inv);
        *reinterpret_cast<float4*>(&wA[lane * 4]) = av;
        __syncwarp();

        float o = 0.f;
#pragma unroll
        for (int k4 = 0; k4 < 128; k4 += 4) {
            float4 a = *reinterpret_cast<const float4*>(&wA[k4]);
            float4 wv = *reinterpret_cast<const float4*>(&sWt[lane * 132 + k4]);
            o += a.x * wv.x + a.y * wv.y + a.z * wv.z + a.w * wv.w;
        }
        float v = o + sb[lane];
        out[(size_t)n * 32 + lane] = 0.5f * v * (1.f + erff(v * 0.70710678118f));
        __syncwarp();
    }
}

extern "C" void kernel_launch(void* const* d_in, const int* in_sizes, int n_in,
                              void* d_out, int out_size) {
    const float* NF = (const float*)d_in[0];   // node_features (N,128)
    const int*   EI = (const int*)  d_in[1];   // edge_index (E,2)
    const float* EF = (const float*)d_in[2];   // edge_features (E,32)
    const float* Wn = (const float*)d_in[3];   // W_node (128,128)
    const float* We = (const float*)d_in[4];   // W_edge (32,128)
    const float* AK = (const float*)d_in[5];   // attn_kernel (4,96)
    const float* Wo = (const float*)d_in[6];   // W_out (128,32)
    const float* bo = (const float*)d_in[7];   // b_out (32,)
    float* out = (float*)d_out;                // (N,32)

    k_prep<<<1, 256>>>(We, AK, Wn);
    k_zero_cnt<<<(N_NODES + 255) / 256, 256>>>();
    k_hist<<<N_EDGES / 256, 256>>>(EI);
    k_scan_blocks<<<SCAN_BLOCKS, 1024>>>();
    k_scan_part<<<1, 128>>>();
    k_scan_add<<<SCAN_BLOCKS, 1024>>>();
    k_node_gemm<<<(N_NODES + 63) / 64, 256>>>(NF, AK);
    k_permute<<<N_EDGES / 64, 256>>>(EI, EF);
    k_agg_out<<<1184, 256>>>(Wo, bo, out);
}

// round 6
// speedup vs baseline: 1.1467x; 1.1467x over previous
#include <cuda_runtime.h>
#include <cuda_fp16.h>
#include <mma.h>
#include <math.h>

using namespace nvcuda;

#define N_NODES 100000
#define N_EDGES 1600000
#define F_IN    128
#define F_E     32
#define DH      128   // D*H
#define NH      4     // heads
#define FULLM   0xffffffffu
#define SCAN_BLOCKS 98   // ceil(100000/1024)

// -------- scratch (static device globals; no allocation allowed) --------
__device__ __half2 g_np_h[(size_t)N_NODES * 64];      // node_proj fp16, 25.6 MB
__device__ __half  g_W_h[F_IN * DH];                  // W_node in fp16
__device__ float g_ssrc[N_NODES * NH];
__device__ float g_u[NH * F_IN];                      // W_node @ a_src  (per head)
__device__ float g_v[NH * F_E];                       // W_edge @ a_edge (per head)
__device__ int g_cnt[N_NODES];
__device__ int g_rowptr[N_NODES + 1];
__device__ int g_head[N_NODES];
__device__ unsigned long long g_state[SCAN_BLOCKS];   // lookback scan states
__device__ float4 g_p4[N_EDGES];                      // attn numerators, dst-sorted
__device__ int    g_src[N_EDGES];                     // src ids, dst-sorted

// -------- prep: fold weights, convert W_node to fp16, zero cnt/states -----
__global__ void __launch_bounds__(256) k_prep(const float* __restrict__ We,
                                              const float* __restrict__ AK,
                                              const float* __restrict__ Wn) {
    int t = threadIdx.x, b = blockIdx.x;
    if (b == 0) {
        for (int i = t; i < NH * F_IN; i += 256) {        // u[h][k]
            int h = i >> 7, k = i & 127;
            float s = 0.f;
#pragma unroll
            for (int d = 0; d < 32; d++)
                s += Wn[k * DH + h * 32 + d] * AK[h * 96 + d];
            g_u[i] = s;
        }
        if (t < 128) {                                     // v[h][k]
            int h = t >> 5, k = t & 31;
            float s = 0.f;
#pragma unroll
            for (int d = 0; d < 32; d++)
                s += We[k * DH + h * 32 + d] * AK[h * 96 + 64 + d];
            g_v[t] = s;
        }
    } else {
        const int total = F_IN * DH + N_NODES + SCAN_BLOCKS;
        for (int i = (b - 1) * 256 + t; i < total; i += 255 * 256) {
            if (i < F_IN * DH) g_W_h[i] = __float2half_rn(Wn[i]);
            else if (i < F_IN * DH + N_NODES) g_cnt[i - F_IN * DH] = 0;
            else g_state[i - F_IN * DH - N_NODES] = 0ull;
        }
    }
}

// -------- fused: s_src[n,h] = NF[n] . u[h]  AND  dst histogram --------
__global__ void __launch_bounds__(256) k_ssrc_hist(const float* __restrict__ NF,
                                                   const int* __restrict__ EI) {
    int t = threadIdx.x, b = blockIdx.x;
    if (t < 128) {                                   // 12500*128 = 1.6M edges
        int e = b * 128 + t;
        int2 ei = reinterpret_cast<const int2*>(EI)[e];
        atomicAdd(&g_cnt[ei.y], 1);
    }
    int lane = t & 31, w = t >> 5;
    int n = b * 8 + w;                               // 12500*8 = 100000 nodes
    if (n < N_NODES) {
        float4 x = reinterpret_cast<const float4*>(NF)[(size_t)n * 32 + lane];
        float s[4];
#pragma unroll
        for (int h = 0; h < 4; h++) {
            float4 u = reinterpret_cast<const float4*>(g_u)[h * 32 + lane];
            s[h] = x.x * u.x + x.y * u.y + x.z * u.z + x.w * u.w;
        }
#pragma unroll
        for (int o = 16; o >= 1; o >>= 1)
#pragma unroll
            for (int h = 0; h < 4; h++)
                s[h] += __shfl_down_sync(FULLM, s[h], o);
        if (lane == 0)
            reinterpret_cast<float4*>(g_ssrc)[n] = make_float4(s[0], s[1], s[2], s[3]);
    }
}

// -------- single-pass decoupled-lookback scan -> rowptr + head --------
__global__ void __launch_bounds__(1024) k_scan() {
    __shared__ int s[1024];
    __shared__ int sprefix;
    int t = threadIdx.x, b = blockIdx.x;
    int i = b * 1024 + t;
    int v = (i < N_NODES) ? g_cnt[i] : 0;
    s[t] = v;
    __syncthreads();
    for (int o = 1; o < 1024; o <<= 1) {
        int u = (t >= o) ? s[t - o] : 0;
        __syncthreads();
        s[t] += u;
        __syncthreads();
    }
    int excl = s[t] - v;
    int total = s[1023];

    if (t == 0) {
        unsigned long long st = ((b == 0 ? 2ull : 1ull) << 32) | (unsigned)total;
        atomicExch(&g_state[b], st);
        if (b == 0) sprefix = 0;
    }
    if (b > 0 && t < 32) {            // warp 0 lookback
        int lane = t;
        unsigned running = 0;
        int idx = b - 1;
        while (true) {
            int pi = idx - lane;
            unsigned long long sv_ = (pi >= 0) ? atomicAdd(&g_state[pi], 0ull)
                                               : (2ull << 32);
            int flag = (int)(sv_ >> 32);
            unsigned val = (unsigned)sv_;
            unsigned m2 = __ballot_sync(FULLM, flag == 2);
            unsigned m0 = __ballot_sync(FULLM, flag == 0);
            int f2 = m2 ? (__ffs(m2) - 1) : 32;
            int f0 = m0 ? (__ffs(m0) - 1) : 32;
            if (f2 < f0) {
                unsigned c = (lane <= f2) ? val : 0;
#pragma unroll
                for (int o = 16; o >= 1; o >>= 1) c += __shfl_down_sync(FULLM, c, o);
                if (lane == 0) running += c;
                break;
            } else if (f0 < 32) {
                unsigned c = (lane < f0) ? val : 0;
#pragma unroll
                for (int o = 16; o >= 1; o >>= 1) c += __shfl_down_sync(FULLM, c, o);
                if (lane == 0) running += c;
                idx -= f0;
            } else {
                unsigned c = val;
#pragma unroll
                for (int o = 16; o >= 1; o >>= 1) c += __shfl_down_sync(FULLM, c, o);
                if (lane == 0) running += c;
                idx -= 32;
            }
        }
        if (lane == 0) {
            atomicExch(&g_state[b], (2ull << 32) | (unsigned)(running + total));
            sprefix = (int)running;
        }
    }
    __syncthreads();
    int P = sprefix;
    if (i < N_NODES) {
        int r = excl + P;
        g_rowptr[i] = r;
        g_head[i] = r;
    }
    if (b == 0 && t == 0) g_rowptr[N_NODES] = N_EDGES;
}

// -------- permute: p = exp(s_src[src]+s_edge), counting-sort by dst --------
__global__ void __launch_bounds__(256) k_permute(const int* __restrict__ EI,
                                                 const float* __restrict__ EF) {
    __shared__ float sef[64 * 36];    // 64 edges x 32 feats, stride 36
    __shared__ float sv[160];         // v padded stride 40 per head
    __shared__ int2  sEI[64];
    __shared__ float sp[256];
    int t = threadIdx.x;
    int e0 = blockIdx.x * 64;
    if (t < 160) {
        int h = t / 40, kk = t % 40;
        sv[t] = (kk < 32) ? g_v[h * 32 + kk] : 0.f;
    }
    if (t < 64) sEI[t] = reinterpret_cast<const int2*>(EI)[e0 + t];
#pragma unroll
    for (int i = 0; i < 2; i++) {
        int idx = i * 256 + t;
        int el = idx >> 3, c4 = idx & 7;
        float4 v = reinterpret_cast<const float4*>(EF + (size_t)(e0 + el) * F_E)[c4];
        *reinterpret_cast<float4*>(&sef[el * 36 + c4 * 4]) = v;
    }
    __syncthreads();

    {   // thread = (edge, head); LDS.128 dot products
        int el = t >> 2, h = t & 3;
        const float* vh = sv + h * 40;
        float se = 0.f;
#pragma unroll
        for (int j4 = 0; j4 < 8; j4++) {
            float4 f = *reinterpret_cast<const float4*>(&sef[el * 36 + j4 * 4]);
            float4 vv = *reinterpret_cast<const float4*>(&vh[j4 * 4]);
            se += f.x * vv.x + f.y * vv.y + f.z * vv.z + f.w * vv.w;
        }
        int2 ei = sEI[el];
        sp[t] = __expf(g_ssrc[ei.x * 4 + h] + se);
    }
    __syncthreads();

    if (t < 64) {
        int2 ei = sEI[t];
        int pos = atomicAdd(&g_head[ei.y], 1);
        g_p4[pos] = *reinterpret_cast<float4*>(&sp[t * 4]);
        g_src[pos] = ei.x;
    }
}

// -------- node_proj = NF @ W_node via wmma (fp16 in, fp32 acc) --------
__global__ void __launch_bounds__(256) k_node_gemm(const float* __restrict__ NF) {
    __shared__ __half sA[64 * 128];   // 16 KB
    __shared__ float  sC[64 * 128];   // 32 KB
    int t = threadIdx.x;
    int row0 = blockIdx.x * 64;

#pragma unroll
    for (int i = 0; i < 8; i++) {
        int idx = i * 256 + t;
        int r = idx >> 5, c4 = idx & 31;
        int gr = row0 + r;
        float4 v = (gr < N_NODES)
            ? reinterpret_cast<const float4*>(NF)[(size_t)gr * 32 + c4]
            : make_float4(0.f, 0.f, 0.f, 0.f);
        __half2 h01 = __floats2half2_rn(v.x, v.y);
        __half2 h23 = __floats2half2_rn(v.z, v.w);
        uint2 raw;
        raw.x = *reinterpret_cast<unsigned*>(&h01);
        raw.y = *reinterpret_cast<unsigned*>(&h23);
        reinterpret_cast<uint2*>(sA)[idx] = raw;
    }
    __syncthreads();

    int w = t >> 5;
    int wm = w >> 1, wn = w & 1;
    wmma::fragment<wmma::accumulator, 16, 16, 16, float> c[4];
#pragma unroll
    for (int j = 0; j < 4; j++) wmma::fill_fragment(c[j], 0.f);
#pragma unroll
    for (int k = 0; k < 8; k++) {
        wmma::fragment<wmma::matrix_a, 16, 16, 16, __half, wmma::row_major> a;
        wmma::load_matrix_sync(a, sA + (wm * 16) * 128 + k * 16, 128);
#pragma unroll
        for (int j = 0; j < 4; j++) {
            wmma::fragment<wmma::matrix_b, 16, 16, 16, __half, wmma::row_major> bfrag;
            wmma::load_matrix_sync(bfrag, g_W_h + (k * 16) * 128 + wn * 64 + j * 16, 128);
            wmma::mma_sync(c[j], a, bfrag, c[j]);
        }
    }
#pragma unroll
    for (int j = 0; j < 4; j++)
        wmma::store_matrix_sync(sC + (wm * 16) * 128 + wn * 64 + j * 16, c[j],
                                128, wmma::mem_row_major);
    __syncthreads();

    // convert fp32 tile -> fp16 node_proj
#pragma unroll
    for (int i = 0; i < 16; i++) {
        int idx = i * 256 + t;            // half2 index within 64x64
        int r = idx >> 6, c2 = idx & 63;
        int gr = row0 + r;
        if (gr < N_NODES) {
            float2 v = *reinterpret_cast<const float2*>(&sC[r * 128 + c2 * 2]);
            g_np_h[(size_t)gr * 64 + c2] = __floats2half2_rn(v.x, v.y);
        }
    }
}

// -------- fused gather-aggregate + softmax-normalize + W_out + gelu --------
__global__ void __launch_bounds__(256) k_agg_out(const float* __restrict__ Wo,
                                                 const float* __restrict__ bo,
                                                 float* __restrict__ out) {
    __shared__ float sWt[32 * 132];   // W_out transposed [col][k], padded
    __shared__ float sb[32];
    __shared__ float s_p[8 * 128];
    __shared__ int   s_src[8 * 32];
    __shared__ float s_A[8 * 128];
    int t = threadIdx.x, lane = t & 31, w = t >> 5;
    for (int idx = t; idx < 4096; idx += 256) {
        int k = idx >> 5, col = idx & 31;
        sWt[col * 132 + k] = Wo[idx];
    }
    if (t < 32) sb[t] = bo[t];
    __syncthreads();

    float* wp = s_p + w * 128;
    int* wsrc = s_src + w * 32;
    float* wA = s_A + w * 128;
    int h = lane >> 3;
    const uint2* np2 = reinterpret_cast<const uint2*>(g_np_h);

    for (int n = blockIdx.x * 8 + w; n < N_NODES; n += gridDim.x * 8) {
        int beg = g_rowptr[n];
        int end = g_rowptr[n + 1];
        float a0 = 0.f, a1 = 0.f, a2 = 0.f, a3 = 0.f, ds = 0.f;

        for (int j0 = beg; j0 < end; j0 += 32) {
            int j = j0 + lane;
            if (j < end) {
                *reinterpret_cast<float4*>(&wp[lane * 4]) = g_p4[j];
                wsrc[lane] = g_src[j];
            }
            __syncwarp();
            int m = min(32, end - j0);
#pragma unroll 4
            for (int q = 0; q < m; q++) {
                int src = wsrc[q];
                float ph = wp[q * 4 + h];
                uint2 raw = np2[(size_t)src * 32 + lane];
                float2 f01 = __half22float2(*reinterpret_cast<__half2*>(&raw.x));
                float2 f23 = __half22float2(*reinterpret_cast<__half2*>(&raw.y));
                a0 += ph * f01.x;
                a1 += ph * f01.y;
                a2 += ph * f23.x;
                a3 += ph * f23.y;
                ds += ph;
            }
            __syncwarp();
        }

        float inv = 1.f / (ds + 1e-8f);
        float4 av = make_float4(a0 * inv, a1 * inv, a2 * inv, a3 * inv);
        *reinterpret_cast<float4*>(&wA[lane * 4]) = av;
        __syncwarp();

        float o = 0.f;
#pragma unroll
        for (int k4 = 0; k4 < 128; k4 += 4) {
            float4 a = *reinterpret_cast<const float4*>(&wA[k4]);
            float4 wv = *reinterpret_cast<const float4*>(&sWt[lane * 132 + k4]);
            o += a.x * wv.x + a.y * wv.y + a.z * wv.z + a.w * wv.w;
        }
        float v = o + sb[lane];
        out[(size_t)n * 32 + lane] = 0.5f * v * (1.f + erff(v * 0.70710678118f));
        __syncwarp();
    }
}

extern "C" void kernel_launch(void* const* d_in, const int* in_sizes, int n_in,
                              void* d_out, int out_size) {
    const float* NF = (const float*)d_in[0];   // node_features (N,128)
    const int*   EI = (const int*)  d_in[1];   // edge_index (E,2)
    const float* EF = (const float*)d_in[2];   // edge_features (E,32)
    const float* Wn = (const float*)d_in[3];   // W_node (128,128)
    const float* We = (const float*)d_in[4];   // W_edge (32,128)
    const float* AK = (const float*)d_in[5];   // attn_kernel (4,96)
    const float* Wo = (const float*)d_in[6];   // W_out (128,32)
    const float* bo = (const float*)d_in[7];   // b_out (32,)
    float* out = (float*)d_out;                // (N,32)

    k_prep<<<256, 256>>>(We, AK, Wn);
    k_ssrc_hist<<<12500, 256>>>(NF, EI);
    k_scan<<<SCAN_BLOCKS, 1024>>>();
    k_permute<<<N_EDGES / 64, 256>>>(EI, EF);         // profiled slot (index 3)
    k_node_gemm<<<(N_NODES + 63) / 64, 256>>>(NF);
    k_agg_out<<<1184, 256>>>(Wo, bo, out);
}

// round 7
// speedup vs baseline: 1.2107x; 1.0557x over previous
#include <cuda_runtime.h>
#include <cuda_fp16.h>
#include <mma.h>
#include <math.h>

using namespace nvcuda;

#define N_NODES 100000
#define N_EDGES 1600000
#define F_IN    128
#define F_E     32
#define DH      128   // D*H
#define NH      4     // heads
#define FULLM   0xffffffffu
#define SCAN_BLOCKS 98          // ceil(100000/1024)
#define HIST_BLOCKS 6250        // 6250*256 = 1.6M edges
#define GEMM_TILES  1563        // ceil(100000/64)

// -------- scratch (static device globals; zero-initialized at load) --------
__device__ __half2 g_np_h[(size_t)N_NODES * 64];      // node_proj fp16, 25.6 MB
__device__ float g_ssrc[N_NODES * NH];
__device__ float g_v[NH * F_E];                       // W_edge @ a_edge (per head)
__device__ int g_cnt[N_NODES];                        // zeroed by prev run's agg_out
__device__ int g_rowptr[N_NODES + 1];
__device__ int g_head[N_NODES];
__device__ unsigned long long g_state[SCAN_BLOCKS];   // zeroed by prev run's agg_out
__device__ float4 g_p4[N_EDGES];                      // attn numerators, dst-sorted
__device__ int    g_src[N_EDGES];                     // src ids, dst-sorted

static __device__ __forceinline__ unsigned sm32(const void* p) {
    return (unsigned)__cvta_generic_to_shared(p);
}

// ===== launch 0: hist + node GEMM (wmma, fused ssrc epilogue) + v-fold =====
__global__ void __launch_bounds__(256) k_front(const float* __restrict__ NF,
                                               const int* __restrict__ EI,
                                               const float* __restrict__ Wn,
                                               const float* __restrict__ We,
                                               const float* __restrict__ AK) {
    __shared__ __align__(16) unsigned char sraw[49152];
    int t = threadIdx.x, b = blockIdx.x;

    if (b < HIST_BLOCKS) {                       // ---- dst histogram ----
        int e = b * 256 + t;
        int2 ei = reinterpret_cast<const int2*>(EI)[e];
        atomicAdd(&g_cnt[ei.y], 1);
        return;
    }
    if (b == HIST_BLOCKS + GEMM_TILES) {         // ---- fold v = We@a_edge ----
        if (t < 128) {
            int h = t >> 5, k = t & 31;
            float s = 0.f;
#pragma unroll
            for (int d = 0; d < 32; d++)
                s += We[k * DH + h * 32 + d] * AK[h * 96 + 64 + d];
            g_v[t] = s;
        }
        return;
    }

    // ---- GEMM tile: 64 rows of node_proj + ssrc scores ----
    int row0 = (b - HIST_BLOCKS) * 64;
    __half* sW = reinterpret_cast<__half*>(sraw);            // 128x128 = 32 KB
    __half* sA = reinterpret_cast<__half*>(sraw + 32768);    // 64x128  = 16 KB
    float*  sC = reinterpret_cast<float*>(sraw + 32768);     // 64x64 f32 reuse

    // convert W to fp16 smem (8192 half2)
#pragma unroll
    for (int i = 0; i < 32; i++) {
        int idx = i * 256 + t;
        float2 w2 = reinterpret_cast<const float2*>(Wn)[idx];
        reinterpret_cast<__half2*>(sW)[idx] = __floats2half2_rn(w2.x, w2.y);
    }
    // load + convert A tile (2048 float4)
#pragma unroll
    for (int i = 0; i < 8; i++) {
        int idx = i * 256 + t;
        int r = idx >> 5, c4 = idx & 31;
        int gr = row0 + r;
        float4 v = (gr < N_NODES)
            ? reinterpret_cast<const float4*>(NF)[(size_t)gr * 32 + c4]
            : make_float4(0.f, 0.f, 0.f, 0.f);
        __half2 h01 = __floats2half2_rn(v.x, v.y);
        __half2 h23 = __floats2half2_rn(v.z, v.w);
        uint2 raw;
        raw.x = *reinterpret_cast<unsigned*>(&h01);
        raw.y = *reinterpret_cast<unsigned*>(&h23);
        reinterpret_cast<uint2*>(sA)[idx] = raw;
    }
    __syncthreads();

    int w = t >> 5, wm = w >> 1, wn = w & 1;
    wmma::fragment<wmma::accumulator, 16, 16, 16, float> c[4];
#pragma unroll
    for (int j = 0; j < 4; j++) wmma::fill_fragment(c[j], 0.f);
#pragma unroll
    for (int k = 0; k < 8; k++) {
        wmma::fragment<wmma::matrix_a, 16, 16, 16, __half, wmma::row_major> a;
        wmma::load_matrix_sync(a, sA + (wm * 16) * 128 + k * 16, 128);
#pragma unroll
        for (int j = 0; j < 4; j++) {
            wmma::fragment<wmma::matrix_b, 16, 16, 16, __half, wmma::row_major> bf;
            wmma::load_matrix_sync(bf, sW + (k * 16) * 128 + wn * 64 + j * 16, 128);
            wmma::mma_sync(c[j], a, bf, c[j]);
        }
    }

    // two column-half passes through the 16 KB sC buffer
#pragma unroll
    for (int jh = 0; jh < 2; jh++) {
        __syncthreads();
        if (wn == jh) {
#pragma unroll
            for (int j = 0; j < 4; j++)
                wmma::store_matrix_sync(sC + (wm * 16) * 64 + j * 16, c[j],
                                        64, wmma::mem_row_major);
        }
        __syncthreads();
        // fp16 node_proj write (cols jh*64 .. jh*64+63)
#pragma unroll
        for (int i = 0; i < 8; i++) {
            int idx = i * 256 + t;
            int r = idx >> 5, c2 = idx & 31;
            int gr = row0 + r;
            if (gr < N_NODES) {
                float2 v = reinterpret_cast<const float2*>(sC)[r * 32 + c2];
                g_np_h[(size_t)gr * 64 + jh * 32 + c2] = __floats2half2_rn(v.x, v.y);
            }
        }
        // ssrc for heads jh*2, jh*2+1 (s_dst cancels in segment softmax)
        if (t < 128) {
            int r = t >> 1, hh = t & 1, h = jh * 2 + hh;
            int gr = row0 + r;
            if (gr < N_NODES) {
                const float4* akp = reinterpret_cast<const float4*>(AK + h * 96);
                const float4* cr = reinterpret_cast<const float4*>(sC + r * 64 + hh * 32);
                float s = 0.f;
#pragma unroll
                for (int k4 = 0; k4 < 8; k4++) {
                    float4 a = cr[k4];
                    float4 ak = akp[k4];
                    s += a.x * ak.x + a.y * ak.y + a.z * ak.z + a.w * ak.w;
                }
                g_ssrc[gr * 4 + h] = s;
            }
        }
    }
}

// ===== launch 1: single-pass decoupled-lookback scan -> rowptr + head =====
__global__ void __launch_bounds__(1024) k_scan() {
    __shared__ int s[1024];
    __shared__ int sprefix;
    int t = threadIdx.x, b = blockIdx.x;
    int i = b * 1024 + t;
    int v = (i < N_NODES) ? g_cnt[i] : 0;
    s[t] = v;
    __syncthreads();
    for (int o = 1; o < 1024; o <<= 1) {
        int u = (t >= o) ? s[t - o] : 0;
        __syncthreads();
        s[t] += u;
        __syncthreads();
    }
    int excl = s[t] - v;
    int total = s[1023];

    if (t == 0) {
        unsigned long long st = ((b == 0 ? 2ull : 1ull) << 32) | (unsigned)total;
        atomicExch(&g_state[b], st);
        if (b == 0) sprefix = 0;
    }
    if (b > 0 && t < 32) {
        int lane = t;
        unsigned running = 0;
        int idx = b - 1;
        while (true) {
            int pi = idx - lane;
            unsigned long long sv_ = (pi >= 0) ? atomicAdd(&g_state[pi], 0ull)
                                               : (2ull << 32);
            int flag = (int)(sv_ >> 32);
            unsigned val = (unsigned)sv_;
            unsigned m2 = __ballot_sync(FULLM, flag == 2);
            unsigned m0 = __ballot_sync(FULLM, flag == 0);
            int f2 = m2 ? (__ffs(m2) - 1) : 32;
            int f0 = m0 ? (__ffs(m0) - 1) : 32;
            if (f2 < f0) {
                unsigned cc = (lane <= f2) ? val : 0;
#pragma unroll
                for (int o = 16; o >= 1; o >>= 1) cc += __shfl_down_sync(FULLM, cc, o);
                if (lane == 0) running += cc;
                break;
            } else if (f0 < 32) {
                unsigned cc = (lane < f0) ? val : 0;
#pragma unroll
                for (int o = 16; o >= 1; o >>= 1) cc += __shfl_down_sync(FULLM, cc, o);
                if (lane == 0) running += cc;
                idx -= f0;
            } else {
                unsigned cc = val;
#pragma unroll
                for (int o = 16; o >= 1; o >>= 1) cc += __shfl_down_sync(FULLM, cc, o);
                if (lane == 0) running += cc;
                idx -= 32;
            }
        }
        if (lane == 0) {
            atomicExch(&g_state[b], (2ull << 32) | (unsigned)(running + total));
            sprefix = (int)running;
        }
    }
    __syncthreads();
    int P = sprefix;
    if (i < N_NODES) {
        int r = excl + P;
        g_rowptr[i] = r;
        g_head[i] = r;
    }
    if (b == 0 && t == 0) g_rowptr[N_NODES] = N_EDGES;
}

// ===== launch 2: permute — p = exp(ssrc[src]+s_edge), counting-sort by dst
__global__ void __launch_bounds__(256) k_permute(const int* __restrict__ EI,
                                                 const float* __restrict__ EF) {
    __shared__ float sef[128 * 36];   // 128 edges x 32 feats, stride 36 (18.4 KB)
    __shared__ float sv[160];         // v padded stride 40 per head
    __shared__ int2  sEI[128];
    __shared__ float sp[512];
    int t = threadIdx.x;
    int e0 = blockIdx.x * 128;
    if (t < 160) {
        int h = t / 40, kk = t % 40;
        sv[t] = (kk < 32) ? g_v[h * 32 + kk] : 0.f;
    }
    // issue ssrc gathers EARLY (hide L2 latency under EF staging)
    int el0 = t >> 2, el1 = 64 + (t >> 2), h = t & 3;
    int2 ei0 = reinterpret_cast<const int2*>(EI)[e0 + el0];
    int2 ei1 = reinterpret_cast<const int2*>(EI)[e0 + el1];
    float ss0 = g_ssrc[ei0.x * 4 + h];
    float ss1 = g_ssrc[ei1.x * 4 + h];
    if (t < 128) sEI[t] = reinterpret_cast<const int2*>(EI)[e0 + t];
#pragma unroll
    for (int i = 0; i < 4; i++) {
        int idx = i * 256 + t;
        int el = idx >> 3, c4 = idx & 7;
        float4 v = reinterpret_cast<const float4*>(EF + (size_t)(e0 + el) * F_E)[c4];
        *reinterpret_cast<float4*>(&sef[el * 36 + c4 * 4]) = v;
    }
    __syncthreads();

    {   // two (edge, head) pairs per thread; LDS.128 dots
        const float* vh = sv + h * 40;
        float se0 = 0.f, se1 = 0.f;
#pragma unroll
        for (int j4 = 0; j4 < 8; j4++) {
            float4 vv = *reinterpret_cast<const float4*>(&vh[j4 * 4]);
            float4 f0 = *reinterpret_cast<const float4*>(&sef[el0 * 36 + j4 * 4]);
            float4 f1 = *reinterpret_cast<const float4*>(&sef[el1 * 36 + j4 * 4]);
            se0 += f0.x * vv.x + f0.y * vv.y + f0.z * vv.z + f0.w * vv.w;
            se1 += f1.x * vv.x + f1.y * vv.y + f1.z * vv.z + f1.w * vv.w;
        }
        sp[t] = __expf(ss0 + se0);
        sp[t + 256] = __expf(ss1 + se1);
    }
    __syncthreads();

    if (t < 128) {
        int2 ei = sEI[t];
        int pos = atomicAdd(&g_head[ei.y], 1);
        g_p4[pos] = *reinterpret_cast<float4*>(&sp[t * 4]);
        g_src[pos] = ei.x;
    }
}

// ===== launch 3 (PROFILED): gather-aggregate + normalize + W_out + gelu ====
__global__ void __launch_bounds__(256) k_agg_out(const float* __restrict__ Wo,
                                                 const float* __restrict__ bo,
                                                 float* __restrict__ out) {
    __shared__ float sWt[32 * 132];     // W_out transposed, padded (16.9 KB)
    __shared__ float sb[32];
    __shared__ float s_p[2 * 8 * 128];  // double-buffered record stage (8 KB)
    __shared__ int   s_src[2 * 8 * 32]; // (2 KB)
    __shared__ float s_A[8 * 128];
    int t = threadIdx.x, lane = t & 31, w = t >> 5;

    // re-zero hist/scan state for the NEXT run (invariant restored per call)
    {
        int zi = blockIdx.x * 256 + t;
        if (zi < N_NODES) g_cnt[zi] = 0;
        if (blockIdx.x == 1183 && t < SCAN_BLOCKS) g_state[t] = 0ull;
    }

    for (int idx = t; idx < 4096; idx += 256) {
        int k = idx >> 5, col = idx & 31;
        sWt[col * 132 + k] = Wo[idx];
    }
    if (t < 32) sb[t] = bo[t];
    __syncthreads();

    float* wA = s_A + w * 128;
    int h = lane >> 3;
    const uint2* np2 = reinterpret_cast<const uint2*>(g_np_h);

    for (int n = blockIdx.x * 8 + w; n < N_NODES; n += gridDim.x * 8) {
        int beg = g_rowptr[n];
        int end = g_rowptr[n + 1];
        float a0 = 0.f, a1 = 0.f, a2 = 0.f, a3 = 0.f, ds = 0.f;

        // prefetch chunk 0
        {
            int j = beg + lane;
            if (j < end) {
                unsigned ap = sm32(s_p + (0 * 8 + w) * 128 + lane * 4);
                asm volatile("cp.async.ca.shared.global [%0], [%1], 16;"
                             :: "r"(ap), "l"(g_p4 + j));
                unsigned as = sm32(s_src + (0 * 8 + w) * 32 + lane);
                asm volatile("cp.async.ca.shared.global [%0], [%1], 4;"
                             :: "r"(as), "l"(g_src + j));
            }
            asm volatile("cp.async.commit_group;" ::: "memory");
        }

        int buf = 0;
        for (int j0 = beg; j0 < end; j0 += 32) {
            asm volatile("cp.async.wait_group 0;" ::: "memory");
            __syncwarp();
            int nj0 = j0 + 32;
            if (nj0 < end) {   // prefetch next chunk into other buffer
                int j = nj0 + lane;
                if (j < end) {
                    unsigned ap = sm32(s_p + ((buf ^ 1) * 8 + w) * 128 + lane * 4);
                    asm volatile("cp.async.ca.shared.global [%0], [%1], 16;"
                                 :: "r"(ap), "l"(g_p4 + j));
                    unsigned as = sm32(s_src + ((buf ^ 1) * 8 + w) * 32 + lane);
                    asm volatile("cp.async.ca.shared.global [%0], [%1], 4;"
                                 :: "r"(as), "l"(g_src + j));
                }
            }
            asm volatile("cp.async.commit_group;" ::: "memory");

            const float* wp = s_p + (buf * 8 + w) * 128;
            const int* ws = s_src + (buf * 8 + w) * 32;
            int m = min(32, end - j0);
#pragma unroll 8
            for (int q = 0; q < m; q++) {
                int src = ws[q];
                float ph = wp[q * 4 + h];
                uint2 raw = np2[(size_t)src * 32 + lane];
                float2 f01 = __half22float2(*reinterpret_cast<__half2*>(&raw.x));
                float2 f23 = __half22float2(*reinterpret_cast<__half2*>(&raw.y));
                a0 += ph * f01.x;
                a1 += ph * f01.y;
                a2 += ph * f23.x;
                a3 += ph * f23.y;
                ds += ph;
            }
            buf ^= 1;
        }

        float inv = 1.f / (ds + 1e-8f);
        float4 av = make_float4(a0 * inv, a1 * inv, a2 * inv, a3 * inv);
        *reinterpret_cast<float4*>(&wA[lane * 4]) = av;
        __syncwarp();

        float o = 0.f;
#pragma unroll
        for (int k4 = 0; k4 < 128; k4 += 4) {
            float4 a = *reinterpret_cast<const float4*>(&wA[k4]);
            float4 wv = *reinterpret_cast<const float4*>(&sWt[lane * 132 + k4]);
            o += a.x * wv.x + a.y * wv.y + a.z * wv.z + a.w * wv.w;
        }
        float v = o + sb[lane];
        out[(size_t)n * 32 + lane] = 0.5f * v * (1.f + erff(v * 0.70710678118f));
        __syncwarp();
    }
}

extern "C" void kernel_launch(void* const* d_in, const int* in_sizes, int n_in,
                              void* d_out, int out_size) {
    const float* NF = (const float*)d_in[0];   // node_features (N,128)
    const int*   EI = (const int*)  d_in[1];   // edge_index (E,2)
    const float* EF = (const float*)d_in[2];   // edge_features (E,32)
    const float* Wn = (const float*)d_in[3];   // W_node (128,128)
    const float* We = (const float*)d_in[4];   // W_edge (32,128)
    const float* AK = (const float*)d_in[5];   // attn_kernel (4,96)
    const float* Wo = (const float*)d_in[6];   // W_out (128,32)
    const float* bo = (const float*)d_in[7];   // b_out (32,)
    float* out = (float*)d_out;                // (N,32)

    k_front<<<HIST_BLOCKS + GEMM_TILES + 1, 256>>>(NF, EI, Wn, We, AK);
    k_scan<<<SCAN_BLOCKS, 1024>>>();
    k_permute<<<N_EDGES / 128, 256>>>(EI, EF);
    k_agg_out<<<1184, 256>>>(Wo, bo, out);    // profiled slot (index 3)
}